// round 4
// baseline (speedup 1.0000x reference)
#include <cuda_runtime.h>

// CropAndResize: image (8,256,200,200) f32 NCHW, boxes (512,4) [y1,x1,y2,x2],
// box_indices (512,) int32 -> out (512,256,14,14) f32. Bilinear, extrap 0.
//
// R4: SMEM-stage one full channel plane per block (sequential 128B DRAM reads,
// each plane read exactly once), gather via LDS. Pre-kernels: counting-sort
// boxes by image + per-box interpolation tables.

#define IH 200
#define IW 200
#define CROP 14
#define NCH 256
#define NBOX 512
#define NIMG 8
#define PLANE (IH * IW)            // 40000 floats
#define POS (CROP * CROP)          // 196
#define TPB 1024
#define MAXB 128                   // boxes per table pass
#define BOX_GRP 5                  // boxes gathered concurrently (5*196=980<=1024)

struct Tab { short i0, i1; float l; };   // 8 bytes

__device__ int d_perm[NBOX];
__device__ int d_img_off[NIMG + 1];
__device__ Tab d_ytab[NBOX * CROP];
__device__ Tab d_xtab[NBOX * CROP];
__device__ unsigned d_vy[NBOX];
__device__ unsigned d_vx[NBOX];

__global__ __launch_bounds__(NBOX) void sort_boxes_kernel(
    const int* __restrict__ box_idx)
{
    __shared__ int cnt[NIMG];
    __shared__ int off[NIMG + 1];
    const int tid = threadIdx.x;
    if (tid < NIMG) cnt[tid] = 0;
    __syncthreads();
    const int b = box_idx[tid];
    atomicAdd(&cnt[b], 1);
    __syncthreads();
    if (tid == 0) {
        int s = 0;
        for (int i = 0; i < NIMG; ++i) { off[i] = s; s += cnt[i]; }
        off[NIMG] = s;
    }
    __syncthreads();
    if (tid <= NIMG) d_img_off[tid] = off[tid];
    __syncthreads();
    const int pos = atomicAdd(&off[b], 1);   // bucket-internal order irrelevant
    d_perm[pos] = tid;
}

// One warp per box: lanes 0..13 x-axis, 14..27 y-axis.
__global__ __launch_bounds__(32) void build_tables_kernel(
    const float* __restrict__ boxes)
{
    const int n = blockIdx.x;
    const int lane = threadIdx.x;
    const bool active = lane < 2 * CROP;
    const bool isx = lane < CROP;
    const int k = isx ? lane : lane - CROP;
    int valid = 0;
    Tab t = {0, 0, 0.0f};
    if (active) {
        const float a1 = boxes[n * 4 + (isx ? 1 : 0)];
        const float a2 = boxes[n * 4 + (isx ? 3 : 2)];
        const float D  = isx ? (float)(IW - 1) : (float)(IH - 1);
        const float scale = (a2 - a1) * D * (1.0f / (CROP - 1));
        const float v = a1 * D + (float)k * scale;
        valid = (v >= 0.0f) && (v <= D);
        const float fl = floorf(v);
        const float ce = ceilf(v);
        int i0 = (int)fminf(fmaxf(fl, 0.0f), D);
        int i1 = (int)fminf(fmaxf(ce, 0.0f), D);
        t.i0 = (short)i0; t.i1 = (short)i1; t.l = v - fl;
    }
    const unsigned b = __ballot_sync(0xFFFFFFFF, active && valid);
    if (active) {
        if (isx) d_xtab[n * CROP + k] = t;
        else     d_ytab[n * CROP + k] = t;
    }
    if (lane == 0) {
        d_vx[n] = b & 0x3FFFu;
        d_vy[n] = (b >> CROP) & 0x3FFFu;
    }
}

// Dynamic smem layout
#define SM_PLANE_BYTES (PLANE * 4)                    // 160000
#define SM_YTAB_OFF    SM_PLANE_BYTES
#define SM_XTAB_OFF    (SM_YTAB_OFF + MAXB * CROP * 8)
#define SM_NLIST_OFF   (SM_XTAB_OFF + MAXB * CROP * 8)
#define SM_VY_OFF      (SM_NLIST_OFF + MAXB * 4)
#define SM_VX_OFF      (SM_VY_OFF + MAXB * 4)
#define SM_TOTAL       (SM_VX_OFF + MAXB * 4)         // 190208 bytes

__global__ __launch_bounds__(TPB, 1) void crop_resize_kernel(
    const float* __restrict__ image,
    float*       __restrict__ out)
{
    extern __shared__ char smem[];
    float*    plane = (float*)smem;
    Tab*      ytab  = (Tab*)(smem + SM_YTAB_OFF);
    Tab*      xtab  = (Tab*)(smem + SM_XTAB_OFF);
    int*      nlist = (int*)(smem + SM_NLIST_OFF);
    unsigned* vys   = (unsigned*)(smem + SM_VY_OFF);
    unsigned* vxs   = (unsigned*)(smem + SM_VX_OFF);

    const int img = blockIdx.x >> 8;     // concurrent blocks: same image,
    const int c   = blockIdx.x & 255;    // different channels -> disjoint planes
    const int tid = threadIdx.x;

    // Stream the whole channel plane into SMEM (sequential 128B reads).
    {
        const float4* src = (const float4*)(image + ((size_t)img * NCH + c) * PLANE);
        float4* dst = (float4*)plane;
        #pragma unroll 4
        for (int i = tid; i < PLANE / 4; i += TPB)
            dst[i] = __ldcs(src + i);
    }

    const int o0 = d_img_off[img];
    const int o1 = d_img_off[img + 1];

    // Per-thread fixed decode: myb in [0,5), pos in [0,196)
    const int myb = tid / POS;
    const int pos = tid - myb * POS;
    const int r   = pos / CROP;
    const int col = pos - r * CROP;
    const bool worker = (tid < BOX_GRP * POS);

    float* outc = out + (size_t)c * POS + pos;

    for (int done = o0; done < o1; done += MAXB) {
        const int pb = min(o1 - done, MAXB);

        __syncthreads();   // protect smem tables from previous pass readers
        if (tid < pb) {
            const int n = d_perm[done + tid];
            nlist[tid] = n;
            vys[tid] = d_vy[n];
            vxs[tid] = d_vx[n];
        }
        __syncthreads();
        for (int t = tid; t < pb * CROP; t += TPB) {
            const int bl = t / CROP;
            const int e  = t - bl * CROP;
            const int n  = nlist[bl];
            ytab[t] = d_ytab[n * CROP + e];
            xtab[t] = d_xtab[n * CROP + e];
        }
        __syncthreads();

        for (int base = 0; base < pb; base += BOX_GRP) {
            const int bl = base + myb;
            if (worker && bl < pb) {
                const Tab ty = ytab[bl * CROP + r];
                const Tab tx = xtab[bl * CROP + col];
                const unsigned v = (vys[bl] >> r) & (vxs[bl] >> col) & 1u;
                const float* p0 = plane + (int)ty.i0 * IW;
                const float* p1 = plane + (int)ty.i1 * IW;
                const float tl  = p0[tx.i0];
                const float tr  = p0[tx.i1];
                const float blv = p1[tx.i0];
                const float br  = p1[tx.i1];
                const float top = fmaf(tr - tl,  tx.l, tl);
                const float bot = fmaf(br - blv, tx.l, blv);
                float val = fmaf(bot - top, ty.l, top);
                if (!v) val = 0.0f;
                __stcs(outc + (size_t)nlist[bl] * (NCH * POS), val);
            }
        }
    }
}

extern "C" void kernel_launch(void* const* d_in, const int* in_sizes, int n_in,
                              void* d_out, int out_size)
{
    const float* image   = (const float*)d_in[0];
    const float* boxes   = (const float*)d_in[1];
    const int*   box_idx = (const int*)d_in[2];
    float*       out     = (float*)d_out;

    static bool attr_set = false;
    if (!attr_set) {
        cudaFuncSetAttribute(crop_resize_kernel,
                             cudaFuncAttributeMaxDynamicSharedMemorySize,
                             SM_TOTAL);
        attr_set = true;
    }

    sort_boxes_kernel<<<1, NBOX>>>(box_idx);
    build_tables_kernel<<<NBOX, 32>>>(boxes);
    crop_resize_kernel<<<NIMG * NCH, TPB, SM_TOTAL>>>(image, out);
}